// round 3
// baseline (speedup 1.0000x reference)
#include <cuda_runtime.h>
#include <math.h>

#define D_MODEL 512
#define N_HEADS 8
#define HD      64
#define BATCH   2
#define SEQ     4096
#define MROWS   (BATCH * SEQ)   // 8192

typedef unsigned long long u64;

// ---- packed fp32x2 helpers (sm_100+/sm_103a) -------------------------------
__device__ __forceinline__ u64 pk2(float lo, float hi) {
    u64 r; asm("mov.b64 %0, {%1, %2};" : "=l"(r) : "f"(lo), "f"(hi)); return r;
}
__device__ __forceinline__ u64 dup2(float v) { return pk2(v, v); }
__device__ __forceinline__ float2 up2(u64 v) {
    float2 r; asm("mov.b64 {%0, %1}, %2;" : "=f"(r.x), "=f"(r.y) : "l"(v)); return r;
}
__device__ __forceinline__ void fma2(u64& d, u64 a, u64 b) {
    asm("fma.rn.f32x2 %0, %1, %2, %0;" : "+l"(d) : "l"(a), "l"(b));
}
__device__ __forceinline__ void mul2(u64& d, u64 a, u64 b) {
    asm("mul.rn.f32x2 %0, %1, %2;" : "=l"(d) : "l"(a), "l"(b));
}

// Scratch
__device__ float g_QT[D_MODEL * MROWS];   // Q transposed: [n=512][m=8192]
__device__ float g_KT[D_MODEL * MROWS];   // K transposed: [n=512][m=8192]
__device__ float g_V [MROWS * D_MODEL];   // V natural
__device__ float g_attn[MROWS * D_MODEL]; // attn natural

// ---------------------------------------------------------------------------
// GEMM: C[M,N] = A[M,K] @ B[K,N] + bias ; M=8192, N=K=512
// Block 128x128, K-tile 16, 256 threads, 8x8 micro-tile, f32x2 FMA.
// Accumulators paired along M (natural pairs from As[k][m]).
// ---------------------------------------------------------------------------
__global__ __launch_bounds__(256) void gemm_kernel(
    const float* __restrict__ A, const float* __restrict__ B,
    const float* __restrict__ bias, float* __restrict__ C, int trans_out)
{
    const int M = MROWS, N = D_MODEL, K = D_MODEL;
    __shared__ float As[16][128];   // [k][m]
    __shared__ float Bs[16][128];   // [k][n]

    int tid = threadIdx.x;
    int tx = tid & 15, ty = tid >> 4;
    int bm = blockIdx.y * 128, bn = blockIdx.x * 128;

    int a_row = tid >> 1;           // 0..127
    int a_k0  = (tid & 1) * 8;      // 0 or 8

    u64 acc[4][8];
#pragma unroll
    for (int i = 0; i < 4; i++)
#pragma unroll
        for (int j = 0; j < 8; j++) acc[i][j] = 0ULL;

    const float* Aptr = A + (size_t)(bm + a_row) * K + a_k0;

    for (int kt = 0; kt < K; kt += 16) {
        float4 av0 = *(const float4*)(Aptr + kt);
        float4 av1 = *(const float4*)(Aptr + kt + 4);
        float4 bv[2];
#pragma unroll
        for (int i = 0; i < 2; i++) {
            int slot = tid + i * 256;
            int row = slot >> 5, c4 = slot & 31;
            bv[i] = *(const float4*)&B[(size_t)(kt + row) * N + bn + c4 * 4];
        }
        __syncthreads();
        As[a_k0 + 0][a_row] = av0.x;  As[a_k0 + 1][a_row] = av0.y;
        As[a_k0 + 2][a_row] = av0.z;  As[a_k0 + 3][a_row] = av0.w;
        As[a_k0 + 4][a_row] = av1.x;  As[a_k0 + 5][a_row] = av1.y;
        As[a_k0 + 6][a_row] = av1.z;  As[a_k0 + 7][a_row] = av1.w;
#pragma unroll
        for (int i = 0; i < 2; i++) {
            int slot = tid + i * 256;
            int row = slot >> 5, c4 = slot & 31;
            *(float4*)&Bs[row][c4 * 4] = bv[i];
        }
        __syncthreads();

#pragma unroll
        for (int k = 0; k < 16; k++) {
            ulonglong2 a01 = *(const ulonglong2*)&As[k][ty * 8];
            ulonglong2 a23 = *(const ulonglong2*)&As[k][ty * 8 + 4];
            u64 ap[4] = {a01.x, a01.y, a23.x, a23.y};
            float4 b0 = *(const float4*)&Bs[k][tx * 8];
            float4 b1 = *(const float4*)&Bs[k][tx * 8 + 4];
            u64 bd[8] = {dup2(b0.x), dup2(b0.y), dup2(b0.z), dup2(b0.w),
                         dup2(b1.x), dup2(b1.y), dup2(b1.z), dup2(b1.w)};
#pragma unroll
            for (int i = 0; i < 4; i++)
#pragma unroll
                for (int j = 0; j < 8; j++)
                    fma2(acc[i][j], ap[i], bd[j]);
        }
        __syncthreads();
    }

    if (!trans_out) {
        float4 bb0 = *(const float4*)&bias[bn + tx * 8];
        float4 bb1 = *(const float4*)&bias[bn + tx * 8 + 4];
        float bb[8] = {bb0.x, bb0.y, bb0.z, bb0.w, bb1.x, bb1.y, bb1.z, bb1.w};
#pragma unroll
        for (int r = 0; r < 8; r++) {
            int m = bm + ty * 8 + r;
            int ip = r >> 1, half = r & 1;
            float v[8];
#pragma unroll
            for (int j = 0; j < 8; j++) {
                float2 t = up2(acc[ip][j]);
                v[j] = (half ? t.y : t.x) + bb[j];
            }
            *(float4*)&C[(size_t)m * N + bn + tx * 8]     = make_float4(v[0], v[1], v[2], v[3]);
            *(float4*)&C[(size_t)m * N + bn + tx * 8 + 4] = make_float4(v[4], v[5], v[6], v[7]);
        }
    } else {
#pragma unroll
        for (int j = 0; j < 8; j++) {
            int n = bn + tx * 8 + j;
            float bj = bias[n];
            float2 t0 = up2(acc[0][j]);
            float2 t1 = up2(acc[1][j]);
            float2 t2 = up2(acc[2][j]);
            float2 t3 = up2(acc[3][j]);
            *(float4*)&C[(size_t)n * M + bm + ty * 8] =
                make_float4(t0.x + bj, t0.y + bj, t1.x + bj, t1.y + bj);
            *(float4*)&C[(size_t)n * M + bm + ty * 8 + 4] =
                make_float4(t2.x + bj, t2.y + bj, t3.x + bj, t3.y + bj);
        }
    }
}

// ---------------------------------------------------------------------------
// Flash attention (fp32, f32x2 FMA). Q-tile 128, K-tile 64, 256 threads.
// Per-thread: S micro 8q x 4k, O micro 8q x 4d, accumulators paired along q.
// ---------------------------------------------------------------------------
__global__ __launch_bounds__(256, 2) void flash_kernel(
    const float* __restrict__ QT, const float* __restrict__ KT,
    const float* __restrict__ V, float* __restrict__ O)
{
    extern __shared__ float sm[];
    float (*Qs)[128] = (float(*)[128])(sm);                       // [d][q] 64x128
    float (*Ks)[64]  = (float(*)[64])(sm + 64 * 128);             // [d][k] 64x64
    float (*Vs)[64]  = (float(*)[64])(sm + 64 * 128 + 64 * 64);   // [k][d] 64x64
    float (*Ps)[68]  = (float(*)[68])(sm + 64 * 128 + 2 * 64 * 64); // [q][k] 128x68

    const int M = MROWS;
    int b = blockIdx.z, h = blockIdx.y;
    int q0 = blockIdx.x * 128;
    int tid = threadIdx.x, tx = tid & 15, ty = tid >> 4;
    const float scale = 0.125f;

    // Load Q tile [d][q], scaled: 64x128 = 2048 float4 slots
#pragma unroll
    for (int i = 0; i < 8; i++) {
        int slot = tid + i * 256;
        int d = slot >> 5, q4 = slot & 31;
        float4 v = *(const float4*)&QT[(size_t)(h * HD + d) * M + b * SEQ + q0 + q4 * 4];
        v.x *= scale; v.y *= scale; v.z *= scale; v.w *= scale;
        *(float4*)&Qs[d][q4 * 4] = v;
    }

    u64 o[4][4];
    float mi[8], li[8];
#pragma unroll
    for (int i = 0; i < 4; i++)
#pragma unroll
        for (int j = 0; j < 4; j++) o[i][j] = 0ULL;
#pragma unroll
    for (int r = 0; r < 8; r++) { mi[r] = -1e30f; li[r] = 0.0f; }

    for (int j0 = 0; j0 < SEQ; j0 += 64) {
        __syncthreads();   // prev-iter PV done (and Q stores before first compute)
#pragma unroll
        for (int i = 0; i < 4; i++) {
            int slot = tid + i * 256;
            int r = slot >> 4, c4 = slot & 15;
            *(float4*)&Ks[r][c4 * 4] =
                *(const float4*)&KT[(size_t)(h * HD + r) * M + b * SEQ + j0 + c4 * 4];
            *(float4*)&Vs[r][c4 * 4] =
                *(const float4*)&V[(size_t)(b * SEQ + j0 + r) * D_MODEL + h * HD + c4 * 4];
        }
        __syncthreads();

        // S = Q^T K  (pairs along q)
        u64 s[4][4];
#pragma unroll
        for (int i = 0; i < 4; i++)
#pragma unroll
            for (int j = 0; j < 4; j++) s[i][j] = 0ULL;

#pragma unroll 8
        for (int d = 0; d < 64; d++) {
            ulonglong2 qa = *(const ulonglong2*)&Qs[d][ty * 8];
            ulonglong2 qb = *(const ulonglong2*)&Qs[d][ty * 8 + 4];
            u64 ap[4] = {qa.x, qa.y, qb.x, qb.y};
            float4 kv = *(const float4*)&Ks[d][tx * 4];
            u64 kd[4] = {dup2(kv.x), dup2(kv.y), dup2(kv.z), dup2(kv.w)};
#pragma unroll
            for (int i = 0; i < 4; i++)
#pragma unroll
                for (int j = 0; j < 4; j++)
                    fma2(s[i][j], ap[i], kd[j]);
        }

        // unpack scores
        float sf[8][4];
#pragma unroll
        for (int ip = 0; ip < 4; ip++)
#pragma unroll
            for (int j = 0; j < 4; j++) {
                float2 t = up2(s[ip][j]);
                sf[ip * 2][j] = t.x;
                sf[ip * 2 + 1][j] = t.y;
            }

        // online softmax (reduce over 16 tx lanes)
        float alpha[8];
#pragma unroll
        for (int r = 0; r < 8; r++) {
            float mx = fmaxf(fmaxf(sf[r][0], sf[r][1]), fmaxf(sf[r][2], sf[r][3]));
            mx = fmaxf(mx, __shfl_xor_sync(0xffffffffu, mx, 1));
            mx = fmaxf(mx, __shfl_xor_sync(0xffffffffu, mx, 2));
            mx = fmaxf(mx, __shfl_xor_sync(0xffffffffu, mx, 4));
            mx = fmaxf(mx, __shfl_xor_sync(0xffffffffu, mx, 8));
            float mn = fmaxf(mi[r], mx);
            alpha[r] = __expf(mi[r] - mn);
            mi[r] = mn;
            float rs = 0.0f;
#pragma unroll
            for (int j = 0; j < 4; j++) {
                float p = __expf(sf[r][j] - mn);
                sf[r][j] = p;
                rs += p;
            }
            rs += __shfl_xor_sync(0xffffffffu, rs, 1);
            rs += __shfl_xor_sync(0xffffffffu, rs, 2);
            rs += __shfl_xor_sync(0xffffffffu, rs, 4);
            rs += __shfl_xor_sync(0xffffffffu, rs, 8);
            li[r] = li[r] * alpha[r] + rs;
        }
#pragma unroll
        for (int ip = 0; ip < 4; ip++) {
            u64 ad = pk2(alpha[ip * 2], alpha[ip * 2 + 1]);
#pragma unroll
            for (int j = 0; j < 4; j++) mul2(o[ip][j], o[ip][j], ad);
        }

        // stage P rows
#pragma unroll
        for (int r = 0; r < 8; r++)
            *(float4*)&Ps[ty * 8 + r][tx * 4] =
                make_float4(sf[r][0], sf[r][1], sf[r][2], sf[r][3]);
        __syncthreads();

        // O += P V
#pragma unroll 4
        for (int k = 0; k < 64; k += 2) {
            float2 pr[8];
#pragma unroll
            for (int r = 0; r < 8; r++)
                pr[r] = *(const float2*)&Ps[ty * 8 + r][k];
#pragma unroll
            for (int kk = 0; kk < 2; kk++) {
                float4 vv = *(const float4*)&Vs[k + kk][tx * 4];
                u64 vd[4] = {dup2(vv.x), dup2(vv.y), dup2(vv.z), dup2(vv.w)};
                u64 pq[4];
#pragma unroll
                for (int ip = 0; ip < 4; ip++)
                    pq[ip] = kk ? pk2(pr[ip * 2].y, pr[ip * 2 + 1].y)
                                : pk2(pr[ip * 2].x, pr[ip * 2 + 1].x);
#pragma unroll
                for (int ip = 0; ip < 4; ip++)
#pragma unroll
                    for (int j = 0; j < 4; j++)
                        fma2(o[ip][j], pq[ip], vd[j]);
            }
        }
    }

    // normalize + store
#pragma unroll
    for (int r = 0; r < 8; r++) {
        float inv = 1.0f / li[r];
        int ip = r >> 1, half = r & 1;
        float v[4];
#pragma unroll
        for (int j = 0; j < 4; j++) {
            float2 t = up2(o[ip][j]);
            v[j] = (half ? t.y : t.x) * inv;
        }
        *(float4*)&O[(size_t)(b * SEQ + q0 + ty * 8 + r) * D_MODEL + h * HD + tx * 4] =
            make_float4(v[0], v[1], v[2], v[3]);
    }
}

// ---------------------------------------------------------------------------
extern "C" void kernel_launch(void* const* d_in, const int* in_sizes, int n_in,
                              void* d_out, int out_size)
{
    const float* x  = (const float*)d_in[0];
    const float* Wq = (const float*)d_in[1];
    const float* bq = (const float*)d_in[2];
    const float* Wk = (const float*)d_in[3];
    const float* bk = (const float*)d_in[4];
    const float* Wv = (const float*)d_in[5];
    const float* bv = (const float*)d_in[6];
    const float* Wo = (const float*)d_in[7];
    const float* bo = (const float*)d_in[8];
    float* out = (float*)d_out;

    float *QT, *KT, *Vb, *attn;
    cudaGetSymbolAddress((void**)&QT,   g_QT);
    cudaGetSymbolAddress((void**)&KT,   g_KT);
    cudaGetSymbolAddress((void**)&Vb,   g_V);
    cudaGetSymbolAddress((void**)&attn, g_attn);

    const int smem_flash = (64 * 128 + 2 * 64 * 64 + 128 * 68) * (int)sizeof(float); // 100352
    cudaFuncSetAttribute(flash_kernel,
                         cudaFuncAttributeMaxDynamicSharedMemorySize, smem_flash);

    dim3 ggrid(D_MODEL / 128, MROWS / 128);   // (4, 64)
    gemm_kernel<<<ggrid, 256>>>(x, Wq, bq, QT, 1);
    gemm_kernel<<<ggrid, 256>>>(x, Wk, bk, KT, 1);
    gemm_kernel<<<ggrid, 256>>>(x, Wv, bv, Vb, 0);

    dim3 fgrid(SEQ / 128, N_HEADS, BATCH);    // (32, 8, 2)
    flash_kernel<<<fgrid, 256, smem_flash>>>(QT, KT, Vb, attn);

    gemm_kernel<<<ggrid, 256>>>(attn, Wo, bo, out, 0);
}

// round 5
// speedup vs baseline: 2.6990x; 2.6990x over previous
#include <cuda_runtime.h>
#include <cuda_bf16.h>
#include <stdint.h>

typedef __nv_bfloat16 bf16;
#define SEQ 4096
#define BATCH 2
#define MROWS 8192

__device__ bf16 g_xh[MROWS*512], g_xl[MROWS*512];
__device__ bf16 g_Qh[MROWS*512], g_Ql[MROWS*512];
__device__ bf16 g_Kh[MROWS*512], g_Kl[MROWS*512];
__device__ bf16 g_Vth[512*MROWS], g_Vtl[512*MROWS];
__device__ bf16 g_ATh[MROWS*512], g_ATl[MROWS*512];
__device__ bf16 g_Wh[4][512*512], g_Wl[4][512*512];

static __device__ __forceinline__ uint32_t smem_u32(const void* p){
    uint32_t a; asm("{ .reg .u64 t; cvta.to.shared.u64 t, %1; cvt.u32.u64 %0, t; }":"=r"(a):"l"(p)); return a;
}
__device__ __forceinline__ void cpa16(uint32_t s, const void* g){
    asm volatile("cp.async.ca.shared.global [%0], [%1], 16;"::"r"(s),"l"(g));
}
__device__ __forceinline__ void cp_commit(){ asm volatile("cp.async.commit_group;":::"memory"); }
__device__ __forceinline__ void cp_wait1(){ asm volatile("cp.async.wait_group 1;":::"memory"); }
__device__ __forceinline__ void cp_wait0(){ asm volatile("cp.async.wait_group 0;":::"memory"); }
__device__ __forceinline__ void ldsm4(uint32_t& r0, uint32_t& r1, uint32_t& r2, uint32_t& r3, uint32_t a){
    asm volatile("ldmatrix.sync.aligned.m8n8.x4.shared.b16 {%0,%1,%2,%3}, [%4];"
        :"=r"(r0),"=r"(r1),"=r"(r2),"=r"(r3):"r"(a));
}
__device__ __forceinline__ void mmab(float* c, const uint32_t* a, uint32_t b0, uint32_t b1){
    asm volatile("mma.sync.aligned.m16n8k16.row.col.f32.bf16.bf16.f32 "
        "{%0,%1,%2,%3}, {%4,%5,%6,%7}, {%8,%9}, {%0,%1,%2,%3};"
        :"+f"(c[0]),"+f"(c[1]),"+f"(c[2]),"+f"(c[3])
        :"r"(a[0]),"r"(a[1]),"r"(a[2]),"r"(a[3]),"r"(b0),"r"(b1));
}
__device__ __forceinline__ float ex2f(float x){ float y; asm("ex2.approx.ftz.f32 %0, %1;":"=f"(y):"f"(x)); return y; }
__device__ __forceinline__ uint32_t phl(float a, float b, uint32_t* lo){
    bf16 ha=__float2bfloat16_rn(a), hb=__float2bfloat16_rn(b);
    bf16 la=__float2bfloat16_rn(a-__bfloat162float(ha));
    bf16 lb=__float2bfloat16_rn(b-__bfloat162float(hb));
    *lo=(uint32_t)__bfloat16_as_ushort(la)|((uint32_t)__bfloat16_as_ushort(lb)<<16);
    return (uint32_t)__bfloat16_as_ushort(ha)|((uint32_t)__bfloat16_as_ushort(hb)<<16);
}

// ---- conversions ----------------------------------------------------------
__global__ __launch_bounds__(256) void split_x(const float* __restrict__ x, bf16* xh, bf16* xl){
    int i=blockIdx.x*256+threadIdx.x;
    float4 v=((const float4*)x)[i];
    uint32_t l0,l1,h0=phl(v.x,v.y,&l0),h1=phl(v.z,v.w,&l1);
    ((uint2*)xh)[i]=make_uint2(h0,h1); ((uint2*)xl)[i]=make_uint2(l0,l1);
}
__global__ __launch_bounds__(256) void wsplit(const float* __restrict__ W, bf16* Wth, bf16* Wtl){
    int idx=blockIdx.x*256+threadIdx.x;
    int n=idx>>9, k=idx&511;
    float v=W[(size_t)k*512+n];
    bf16 h=__float2bfloat16_rn(v);
    Wth[idx]=h; Wtl[idx]=__float2bfloat16_rn(v-__bfloat162float(h));
}

// ---- GEMM via mma.sync: C[8192,512] = A @ Wt^T + bias ---------------------
// CTA 128m x 128n, warps 2m x 4n (warp 64x32), k-chunks of 32, double-buffered.
// smem: A [buf][split][128][40bf16] @0 (2*2*10240=40960); B same @40960. 81920 B.
#define G_SMEM 81920
__device__ __forceinline__ void gemm_load(uint32_t sb, int tid, int m0, int n0, int kc, int buf,
    const bf16* Ah, const bf16* Al, const bf16* Bth, const bf16* Btl)
{
    int k0=kc*32;
#pragma unroll
    for(int i=0;i<4;i++){
        int id=tid+i*256, sp=id>>9, r2=id&511, row=r2>>2, q=r2&3;
        cpa16(sb + buf*20480 + sp*10240 + row*80 + q*16,
              (sp?Al:Ah) + (size_t)(m0+row)*512 + k0 + q*8);
    }
#pragma unroll
    for(int i=0;i<4;i++){
        int id=tid+i*256, sp=id>>9, r2=id&511, row=r2>>2, q=r2&3;
        cpa16(sb + 40960 + buf*20480 + sp*10240 + row*80 + q*16,
              (sp?Btl:Bth) + (size_t)(n0+row)*512 + k0 + q*8);
    }
    cp_commit();
}
__global__ __launch_bounds__(256) void gemm_mma(
    const bf16* __restrict__ Ah, const bf16* __restrict__ Al,
    const bf16* __restrict__ Bth, const bf16* __restrict__ Btl,
    const float* __restrict__ bias, int mode, void* o1, void* o2)
{
    extern __shared__ __align__(16) char smem[];
    uint32_t sb=smem_u32(smem);
    int tid=threadIdx.x, wid=tid>>5, lane=tid&31;
    int n0=blockIdx.x*128, m0=blockIdx.y*128;
    int wm=wid>>2, wn=wid&3;
    float acc[4][4][4];
#pragma unroll
    for(int i=0;i<4;i++)
#pragma unroll
        for(int j=0;j<4;j++)
#pragma unroll
            for(int e=0;e<4;e++) acc[i][j][e]=0.f;

    gemm_load(sb,tid,m0,n0,0,0,Ah,Al,Bth,Btl);
    int aRow=lane&15, aKb=(lane>>4)*16;
    int bRow=((lane>>4)&1)*8+(lane&7), bKb=((lane>>3)&1)*16;

    for(int c=0;c<16;c++){
        if(c<15){ gemm_load(sb,tid,m0,n0,c+1,(c+1)&1,Ah,Al,Bth,Btl); cp_wait1(); }
        else cp_wait0();
        __syncthreads();
        uint32_t aB=sb+(c&1)*20480, bB=sb+40960+(c&1)*20480;
#pragma unroll
        for(int kk=0;kk<2;kk++){
            int kb=kk*32;
            uint32_t ah[4][4], al[4][4], bh[2][4], bl[2][4];
#pragma unroll
            for(int mi=0;mi<4;mi++){
                uint32_t ra=aB+(wm*64+mi*16+aRow)*80+kb+aKb;
                ldsm4(ah[mi][0],ah[mi][1],ah[mi][2],ah[mi][3], ra);
                ldsm4(al[mi][0],al[mi][1],al[mi][2],al[mi][3], ra+10240);
            }
#pragma unroll
            for(int p=0;p<2;p++){
                uint32_t rb=bB+(wn*32+p*16+bRow)*80+kb+bKb;
                ldsm4(bh[p][0],bh[p][1],bh[p][2],bh[p][3], rb);
                ldsm4(bl[p][0],bl[p][1],bl[p][2],bl[p][3], rb+10240);
            }
#pragma unroll
            for(int mi=0;mi<4;mi++)
#pragma unroll
                for(int nj=0;nj<4;nj++){
                    int p=nj>>1, e=(nj&1)*2;
                    mmab(acc[mi][nj], ah[mi], bh[p][e],bh[p][e+1]);
                    mmab(acc[mi][nj], al[mi], bh[p][e],bh[p][e+1]);
                    mmab(acc[mi][nj], ah[mi], bl[p][e],bl[p][e+1]);
                }
        }
        __syncthreads();
    }
#pragma unroll
    for(int mi=0;mi<4;mi++){
        int r0=m0+wm*64+mi*16+(lane>>2);
#pragma unroll
        for(int nj=0;nj<4;nj++){
            int cn=n0+wn*32+nj*8+(lane&3)*2;
            float b0=bias[cn], b1=bias[cn+1];
#pragma unroll
            for(int rh=0;rh<2;rh++){
                int r=r0+rh*8;
                float v0=acc[mi][nj][rh*2]+b0, v1=acc[mi][nj][rh*2+1]+b1;
                if(mode==0){
                    *(float2*)((float*)o1+(size_t)r*512+cn)=make_float2(v0,v1);
                } else if(mode==1){
                    uint32_t lo,hi=phl(v0,v1,&lo);
                    *(uint32_t*)((bf16*)o1+(size_t)r*512+cn)=hi;
                    *(uint32_t*)((bf16*)o2+(size_t)r*512+cn)=lo;
                } else {
                    bf16 h0=__float2bfloat16_rn(v0), h1=__float2bfloat16_rn(v1);
                    ((bf16*)o1)[(size_t)cn*MROWS+r]=h0;
                    ((bf16*)o2)[(size_t)cn*MROWS+r]=__float2bfloat16_rn(v0-__bfloat162float(h0));
                    ((bf16*)o1)[(size_t)(cn+1)*MROWS+r]=h1;
                    ((bf16*)o2)[(size_t)(cn+1)*MROWS+r]=__float2bfloat16_rn(v1-__bfloat162float(h1));
                }
            }
        }
    }
}

// ---- Flash attention via mma.sync ----------------------------------------
// Grid (32,8,2), 256 thr. Q-tile 128, K-tile 64. Fixed-shift softmax exp(s-10).
// smem: Q [split][128][72] @0 (36864); P same @36864; KV [buf][4mat][64][72] @73728
// (73728); Ls[128] @147456. Total 147968.
#define F_SMEM 147968
__device__ __forceinline__ void flash_loadkv(uint32_t sb, int tid, int b, int h, int j0, int buf,
    const bf16* Kh, const bf16* Kl, const bf16* Vth, const bf16* Vtl)
{
#pragma unroll
    for(int i=0;i<8;i++){
        int id=tid+i*256, mat=id>>9, r2=id&511, row=r2>>3, q=r2&7;
        const bf16* g;
        if(mat==0)      g=Kh +(size_t)(b*SEQ+j0+row)*512+h*64+q*8;
        else if(mat==1) g=Kl +(size_t)(b*SEQ+j0+row)*512+h*64+q*8;
        else if(mat==2) g=Vth+(size_t)(h*64+row)*MROWS+b*SEQ+j0+q*8;
        else            g=Vtl+(size_t)(h*64+row)*MROWS+b*SEQ+j0+q*8;
        cpa16(sb+73728+buf*36864+mat*9216+row*144+q*16, g);
    }
    cp_commit();
}
__global__ __launch_bounds__(256) void flash_mma(
    const bf16* __restrict__ Qh, const bf16* __restrict__ Ql,
    const bf16* __restrict__ Kh, const bf16* __restrict__ Kl,
    const bf16* __restrict__ Vth, const bf16* __restrict__ Vtl,
    bf16* __restrict__ Oh, bf16* __restrict__ Ol)
{
    extern __shared__ __align__(16) char smem[];
    uint32_t sb=smem_u32(smem);
    int tid=threadIdx.x, wid=tid>>5, lane=tid&31;
    int b=blockIdx.z, h=blockIdx.y, q0=blockIdx.x*128;
    int wm=wid>>2, wk=wid&3;
    float* Ls=(float*)(smem+147456);

    flash_loadkv(sb,tid,b,h,0,0,Kh,Kl,Vth,Vtl);
#pragma unroll
    for(int i=0;i<8;i++){
        int id=tid+i*256, sp=id>>10, r2=id&1023, row=r2>>3, q=r2&7;
        const bf16* g=(sp?Ql:Qh)+(size_t)(b*SEQ+q0+row)*512+h*64+q*8;
        *(uint4*)(smem+sp*18432+row*144+q*16)=*(const uint4*)g;
    }
    if(tid<128) Ls[tid]=0.f;

    const float K1=0.125f*1.44269504f, mK2=-10.0f*1.44269504f;
    int aRow=lane&15, aKb=(lane>>4)*16;
    int bRow=((lane>>4)&1)*8+(lane&7), bKb=((lane>>3)&1)*16;
    float o[4][2][4], ls[4][2];
#pragma unroll
    for(int i=0;i<4;i++){
        ls[i][0]=0.f; ls[i][1]=0.f;
#pragma unroll
        for(int j=0;j<2;j++)
#pragma unroll
            for(int e=0;e<4;e++) o[i][j][e]=0.f;
    }

    for(int t=0;t<64;t++){
        int buf=t&1;
        if(t<63){ flash_loadkv(sb,tid,b,h,(t+1)*64,buf^1,Kh,Kl,Vth,Vtl); cp_wait1(); }
        else cp_wait0();
        __syncthreads();
        uint32_t kvB=sb+73728+buf*36864;
        // QK
        float s[4][2][4];
#pragma unroll
        for(int i=0;i<4;i++)
#pragma unroll
            for(int j=0;j<2;j++)
#pragma unroll
                for(int e=0;e<4;e++) s[i][j][e]=0.f;
#pragma unroll
        for(int kk=0;kk<4;kk++){
            int kb=kk*32;
            uint32_t qh_[4][4], ql_[4][4], kh_[4], kl_[4];
#pragma unroll
            for(int mi=0;mi<4;mi++){
                uint32_t ra=sb+(wm*64+mi*16+aRow)*144+kb+aKb;
                ldsm4(qh_[mi][0],qh_[mi][1],qh_[mi][2],qh_[mi][3], ra);
                ldsm4(ql_[mi][0],ql_[mi][1],ql_[mi][2],ql_[mi][3], ra+18432);
            }
            {
                uint32_t rb=kvB+(wk*16+bRow)*144+kb+bKb;
                ldsm4(kh_[0],kh_[1],kh_[2],kh_[3], rb);
                ldsm4(kl_[0],kl_[1],kl_[2],kl_[3], rb+9216);
            }
#pragma unroll
            for(int mi=0;mi<4;mi++)
#pragma unroll
                for(int nj=0;nj<2;nj++){
                    mmab(s[mi][nj], qh_[mi], kh_[nj*2],kh_[nj*2+1]);
                    mmab(s[mi][nj], ql_[mi], kh_[nj*2],kh_[nj*2+1]);
                    mmab(s[mi][nj], qh_[mi], kl_[nj*2],kl_[nj*2+1]);
                }
        }
        // softmax + P store (bf16 hi/lo)
#pragma unroll
        for(int mi=0;mi<4;mi++)
#pragma unroll
            for(int nj=0;nj<2;nj++){
                float p0=ex2f(fmaf(s[mi][nj][0],K1,mK2));
                float p1=ex2f(fmaf(s[mi][nj][1],K1,mK2));
                float p2=ex2f(fmaf(s[mi][nj][2],K1,mK2));
                float p3=ex2f(fmaf(s[mi][nj][3],K1,mK2));
                ls[mi][0]+=p0+p1; ls[mi][1]+=p2+p3;
                uint32_t l0,h0=phl(p0,p1,&l0), l1,h1=phl(p2,p3,&l1);
                int row=wm*64+mi*16+(lane>>2), col=wk*16+nj*8+(lane&3)*2;
                *(uint32_t*)(smem+36864+row*144+col*2)=h0;
                *(uint32_t*)(smem+36864+18432+row*144+col*2)=l0;
                *(uint32_t*)(smem+36864+(row+8)*144+col*2)=h1;
                *(uint32_t*)(smem+36864+18432+(row+8)*144+col*2)=l1;
            }
        __syncthreads();
        // PV (wk doubles as d-slice)
#pragma unroll
        for(int kk=0;kk<4;kk++){
            int kb=kk*32;
            uint32_t ph_[4][4], pl_[4][4], vh_[4], vl_[4];
#pragma unroll
            for(int mi=0;mi<4;mi++){
                uint32_t ra=sb+36864+(wm*64+mi*16+aRow)*144+kb+aKb;
                ldsm4(ph_[mi][0],ph_[mi][1],ph_[mi][2],ph_[mi][3], ra);
                ldsm4(pl_[mi][0],pl_[mi][1],pl_[mi][2],pl_[mi][3], ra+18432);
            }
            {
                uint32_t rb=kvB+2*9216+(wk*16+bRow)*144+kb+bKb;
                ldsm4(vh_[0],vh_[1],vh_[2],vh_[3], rb);
                ldsm4(vl_[0],vl_[1],vl_[2],vl_[3], rb+9216);
            }
#pragma unroll
            for(int mi=0;mi<4;mi++)
#pragma unroll
                for(int nj=0;nj<2;nj++){
                    mmab(o[mi][nj], ph_[mi], vh_[nj*2],vh_[nj*2+1]);
                    mmab(o[mi][nj], pl_[mi], vh_[nj*2],vh_[nj*2+1]);
                    mmab(o[mi][nj], ph_[mi], vl_[nj*2],vl_[nj*2+1]);
                }
        }
        __syncthreads();
    }
    // reduce row sums across quad lanes + 4 key-warps
#pragma unroll
    for(int mi=0;mi<4;mi++)
#pragma unroll
        for(int rh=0;rh<2;rh++){
            float v=ls[mi][rh];
            v+=__shfl_xor_sync(0xffffffffu,v,1);
            v+=__shfl_xor_sync(0xffffffffu,v,2);
            if((lane&3)==0) atomicAdd(&Ls[wm*64+mi*16+rh*8+(lane>>2)], v);
        }
    __syncthreads();
    // normalize + store bf16 hi/lo (natural layout)
#pragma unroll
    for(int mi=0;mi<4;mi++)
#pragma unroll
        for(int rh=0;rh<2;rh++){
            int row=wm*64+mi*16+rh*8+(lane>>2);
            float inv=1.0f/Ls[row];
            size_t gbase=(size_t)(b*SEQ+q0+row)*512+h*64;
#pragma unroll
            for(int nj=0;nj<2;nj++){
                int cn=wk*16+nj*8+(lane&3)*2;
                float v0=o[mi][nj][rh*2]*inv, v1=o[mi][nj][rh*2+1]*inv;
                uint32_t lo,hi=phl(v0,v1,&lo);
                *(uint32_t*)(Oh+gbase+cn)=hi;
                *(uint32_t*)(Ol+gbase+cn)=lo;
            }
        }
}

// ---------------------------------------------------------------------------
extern "C" void kernel_launch(void* const* d_in, const int* in_sizes, int n_in,
                              void* d_out, int out_size)
{
    const float* x=(const float*)d_in[0];
    const float* W[4]={(const float*)d_in[1],(const float*)d_in[3],(const float*)d_in[5],(const float*)d_in[7]};
    const float* bs[4]={(const float*)d_in[2],(const float*)d_in[4],(const float*)d_in[6],(const float*)d_in[8]};
    float* out=(float*)d_out;

    bf16 *xh,*xl,*Qh,*Ql,*Kh,*Kl,*Vth,*Vtl,*ATh,*ATl,*Wh,*Wl;
    cudaGetSymbolAddress((void**)&xh,g_xh);   cudaGetSymbolAddress((void**)&xl,g_xl);
    cudaGetSymbolAddress((void**)&Qh,g_Qh);   cudaGetSymbolAddress((void**)&Ql,g_Ql);
    cudaGetSymbolAddress((void**)&Kh,g_Kh);   cudaGetSymbolAddress((void**)&Kl,g_Kl);
    cudaGetSymbolAddress((void**)&Vth,g_Vth); cudaGetSymbolAddress((void**)&Vtl,g_Vtl);
    cudaGetSymbolAddress((void**)&ATh,g_ATh); cudaGetSymbolAddress((void**)&ATl,g_ATl);
    cudaGetSymbolAddress((void**)&Wh,g_Wh);   cudaGetSymbolAddress((void**)&Wl,g_Wl);

    cudaFuncSetAttribute(gemm_mma, cudaFuncAttributeMaxDynamicSharedMemorySize, G_SMEM);
    cudaFuncSetAttribute(flash_mma, cudaFuncAttributeMaxDynamicSharedMemorySize, F_SMEM);

    split_x<<<MROWS*512/4/256,256>>>(x,xh,xl);
    for(int i=0;i<4;i++) wsplit<<<512*512/256,256>>>(W[i], Wh+i*512*512, Wl+i*512*512);

    dim3 gg(4, MROWS/128);  // (n-tiles, m-tiles)
    gemm_mma<<<gg,256,G_SMEM>>>(xh,xl,Wh+0*512*512,Wl+0*512*512,bs[0],1,Qh,Ql);
    gemm_mma<<<gg,256,G_SMEM>>>(xh,xl,Wh+1*512*512,Wl+1*512*512,bs[1],1,Kh,Kl);
    gemm_mma<<<gg,256,G_SMEM>>>(xh,xl,Wh+2*512*512,Wl+2*512*512,bs[2],2,Vth,Vtl);

    dim3 fg(SEQ/128, 8, BATCH);  // (32,8,2)
    flash_mma<<<fg,256,F_SMEM>>>(Qh,Ql,Kh,Kl,Vth,Vtl,ATh,ATl);

    gemm_mma<<<gg,256,G_SMEM>>>(ATh,ATl,Wh+3*512*512,Wl+3*512*512,bs[3],0,out,nullptr);
}